// round 3
// baseline (speedup 1.0000x reference)
#include <cuda_runtime.h>
#include <cstdint>

// ---------------------------------------------------------------------------
// Problem constants
// ---------------------------------------------------------------------------
#define BB 2
#define SS 2048
#define DD 1024
#define HH 16
#define RR 64
#define BH (BB * HH)   // 32

// ---------------------------------------------------------------------------
// Packed fp32x2 helpers (Blackwell FFMA2 path — ptxas never auto-fuses this;
// constraint pattern mirrors ptx_helpers.cuh PACK_F32X2/UNPACK_F32X2).
// ---------------------------------------------------------------------------
__device__ __forceinline__ uint64_t pk2(float lo, float hi) {
    uint64_t r;
    asm("mov.b64 %0, {%1, %2};" : "=l"(r)
        : "r"(__float_as_uint(lo)), "r"(__float_as_uint(hi)));
    return r;
}
__device__ __forceinline__ uint64_t bc2(float v) { return pk2(v, v); }
__device__ __forceinline__ float2 upk2(uint64_t v) {
    uint32_t lo, hi;
    asm("mov.b64 {%0, %1}, %2;" : "=r"(lo), "=r"(hi) : "l"(v));
    return make_float2(__uint_as_float(lo), __uint_as_float(hi));
}
__device__ __forceinline__ void fma2(uint64_t& d, uint64_t a, uint64_t b) {
    asm("fma.rn.f32x2 %0, %1, %2, %0;" : "+l"(d) : "l"(a), "l"(b));
}
__device__ __forceinline__ void mul2(uint64_t& d, uint64_t a) {
    asm("mul.rn.f32x2 %0, %0, %1;" : "+l"(d) : "l"(a));
}

// float4 register aliasing: (x,y) and (z,w) as packed b64 pairs, no movs.
union F4U2 { float4 f4; uint64_t u2[2]; };

// ---------------------------------------------------------------------------
// Scratch (static device arrays — runtime allocation is forbidden)
// ---------------------------------------------------------------------------
__device__ float g_Q[BH * SS * RR];
__device__ float g_K[BH * SS * RR];
__device__ float g_V[BH * SS * RR];
__device__ float g_vals[BB * SS * DD];

// ---------------------------------------------------------------------------
// Kernel 1: fused QKV projection (SGEMM 128x128, BK=8, 8x8 -> 8x4-pair).
//   A : q/k/v  [4096 x 1024] row-major
//   W : wqs/wks/wvs [H, D, R]
//   C : g_Q/g_K/g_V in [b,h,s,r]
// ---------------------------------------------------------------------------
__global__ void __launch_bounds__(256) proj_kernel(
    const float* __restrict__ q, const float* __restrict__ k,
    const float* __restrict__ v,
    const float* __restrict__ wq, const float* __restrict__ wk,
    const float* __restrict__ wv)
{
    const int which = blockIdx.z;
    const float* A = (which == 0) ? q : (which == 1) ? k : v;
    const float* W = (which == 0) ? wq : (which == 1) ? wk : wv;
    float* C = (which == 0) ? g_Q : (which == 1) ? g_K : g_V;

    __shared__ float As[8][128];
    __shared__ float Bs[8][128];

    const int t  = threadIdx.x;
    const int m0 = blockIdx.y * 128;
    const int n0 = blockIdx.x * 128;

    const int tr = t >> 4;               // 0..15 (row group of 8)
    const int tc = t & 15;               // 0..15 (col group of 8)

    const int aRow = t >> 1;             // 0..127
    const int aCol = (t & 1) * 4;        // 0 or 4
    const int bRow = t >> 5;             // 0..7
    const int bCol = (t & 31) * 4;       // 0..124

    const int nB = n0 + bCol;
    const int hB = nB >> 6;
    const int rB = nB & 63;

    uint64_t acc[8][4] = {};             // cols tc*8 + {0,1},{2,3},{4,5},{6,7}

    for (int k0 = 0; k0 < DD; k0 += 8) {
        float4 av = *reinterpret_cast<const float4*>(
            &A[(size_t)(m0 + aRow) * DD + k0 + aCol]);
        As[aCol + 0][aRow] = av.x;
        As[aCol + 1][aRow] = av.y;
        As[aCol + 2][aRow] = av.z;
        As[aCol + 3][aRow] = av.w;

        float4 bv = *reinterpret_cast<const float4*>(
            &W[((size_t)hB * DD + k0 + bRow) * RR + rB]);
        *reinterpret_cast<float4*>(&Bs[bRow][bCol]) = bv;

        __syncthreads();
        #pragma unroll
        for (int kk = 0; kk < 8; kk++) {
            float4 ra0 = *reinterpret_cast<const float4*>(&As[kk][tr * 8]);
            float4 ra1 = *reinterpret_cast<const float4*>(&As[kk][tr * 8 + 4]);
            F4U2 rb0, rb1;
            rb0.f4 = *reinterpret_cast<const float4*>(&Bs[kk][tc * 8]);
            rb1.f4 = *reinterpret_cast<const float4*>(&Bs[kk][tc * 8 + 4]);
            uint64_t b2[4] = {rb0.u2[0], rb0.u2[1], rb1.u2[0], rb1.u2[1]};
            uint64_t a2[8] = {bc2(ra0.x), bc2(ra0.y), bc2(ra0.z), bc2(ra0.w),
                              bc2(ra1.x), bc2(ra1.y), bc2(ra1.z), bc2(ra1.w)};
            #pragma unroll
            for (int i = 0; i < 8; i++)
                #pragma unroll
                for (int j = 0; j < 4; j++)
                    fma2(acc[i][j], a2[i], b2[j]);
        }
        __syncthreads();
    }

    const int n = n0 + tc * 8;           // 8-aligned; never straddles a head
    const int h = n >> 6;
    const int r = n & 63;
    #pragma unroll
    for (int i = 0; i < 8; i++) {
        const int m = m0 + tr * 8 + i;
        const int b = m >> 11;
        const int s = m & 2047;
        float* dst = &C[(((size_t)b * HH + h) * SS + s) * RR + r];
        float2 c0 = upk2(acc[i][0]), c1 = upk2(acc[i][1]);
        float2 c2 = upk2(acc[i][2]), c3 = upk2(acc[i][3]);
        *reinterpret_cast<float4*>(dst)     = make_float4(c0.x, c0.y, c1.x, c1.y);
        *reinterpret_cast<float4*>(dst + 4) = make_float4(c2.x, c2.y, c3.x, c3.y);
    }
}

// ---------------------------------------------------------------------------
// Kernel 2: fused attention per (b,h) — flash-style, fp32 throughout.
//   CTA = one 64-row Q tile. 128 threads. 64-row KV tiles.
// ---------------------------------------------------------------------------
__global__ void __launch_bounds__(128) attn_kernel()
{
    const int z  = blockIdx.y;                 // b*H + h
    const int s0 = blockIdx.x * 64;
    const float* Q = g_Q + (size_t)z * SS * RR;
    const float* K = g_K + (size_t)z * SS * RR;
    const float* V = g_V + (size_t)z * SS * RR;

    __shared__ float Qs[64][64];   // [r][q]   (transposed, pre-scaled)
    __shared__ float KVs[64][64];  // K: [r][t] ; V: [k][r]   (reused)
    __shared__ float Ps[64][64];   // [q][k]   (natural)

    const int t  = threadIdx.x;
    const int tr = t >> 4;     // 0..7  -> rows tr*8 .. tr*8+7
    const int tc = t & 15;     // 0..15 -> cols tc*4 .. tc*4+3

    // Load Q transposed into smem, folding in the 1/sqrt(R) scale.
    {
        const int row = t >> 1;
        const int rb  = (t & 1) * 4;
        #pragma unroll
        for (int it = 0; it < 8; it++) {
            const int r0 = it * 8 + rb;
            float4 v4 = *reinterpret_cast<const float4*>(
                &Q[(size_t)(s0 + row) * RR + r0]);
            Qs[r0 + 0][row] = v4.x * 0.125f;
            Qs[r0 + 1][row] = v4.y * 0.125f;
            Qs[r0 + 2][row] = v4.z * 0.125f;
            Qs[r0 + 3][row] = v4.w * 0.125f;
        }
    }

    float m[8], l[8];
    uint64_t o2[8][2];          // output accum, packed pairs over r
    #pragma unroll
    for (int i = 0; i < 8; i++) {
        m[i] = -3.0e38f; l[i] = 0.f;
        o2[i][0] = 0; o2[i][1] = 0;
    }

    for (int kv0 = 0; kv0 < SS; kv0 += 64) {
        __syncthreads();   // prev GEMM2 reads of KVs done (1st iter: no-op)

        // Load K tile transposed: KVs[r][t]
        {
            const int row = t >> 1;
            const int rb  = (t & 1) * 4;
            #pragma unroll
            for (int it = 0; it < 8; it++) {
                const int r0 = it * 8 + rb;
                float4 v4 = *reinterpret_cast<const float4*>(
                    &K[(size_t)(kv0 + row) * RR + r0]);
                KVs[r0 + 0][row] = v4.x;
                KVs[r0 + 1][row] = v4.y;
                KVs[r0 + 2][row] = v4.z;
                KVs[r0 + 3][row] = v4.w;
            }
        }
        __syncthreads();   // also covers initial Qs fill

        // GEMM1: s2[i][jp] += Qs[r][q]-bcast * KVs[r][t]-pair
        uint64_t s2[8][2] = {};
        #pragma unroll 4
        for (int r = 0; r < 64; r++) {
            float4 a0 = *reinterpret_cast<const float4*>(&Qs[r][tr * 8]);
            float4 a1 = *reinterpret_cast<const float4*>(&Qs[r][tr * 8 + 4]);
            F4U2 b; b.f4 = *reinterpret_cast<const float4*>(&KVs[r][tc * 4]);
            uint64_t a2[8] = {bc2(a0.x), bc2(a0.y), bc2(a0.z), bc2(a0.w),
                              bc2(a1.x), bc2(a1.y), bc2(a1.z), bc2(a1.w)};
            #pragma unroll
            for (int i = 0; i < 8; i++) {
                fma2(s2[i][0], a2[i], b.u2[0]);
                fma2(s2[i][1], a2[i], b.u2[1]);
            }
        }

        // Unpack logits, online softmax. Threads sharing a row are 16
        // consecutive lanes (same tr): xor-shuffles 1,2,4,8 reduce the row.
        #pragma unroll
        for (int i = 0; i < 8; i++) {
            float2 p0 = upk2(s2[i][0]), p1 = upk2(s2[i][1]);
            float s[4] = {p0.x, p0.y, p1.x, p1.y};
            float mt = fmaxf(fmaxf(s[0], s[1]), fmaxf(s[2], s[3]));
            #pragma unroll
            for (int off = 1; off < 16; off <<= 1)
                mt = fmaxf(mt, __shfl_xor_sync(0xffffffffu, mt, off));
            const float mn    = fmaxf(m[i], mt);
            const float alpha = __expf(m[i] - mn);
            m[i] = mn;
            float rs = 0.f;
            #pragma unroll
            for (int j = 0; j < 4; j++) {
                s[j] = __expf(s[j] - mn);
                rs += s[j];
            }
            #pragma unroll
            for (int off = 1; off < 16; off <<= 1)
                rs += __shfl_xor_sync(0xffffffffu, rs, off);
            l[i] = l[i] * alpha + rs;
            const uint64_t al2 = bc2(alpha);
            mul2(o2[i][0], al2);
            mul2(o2[i][1], al2);
            // Write P natural: Ps[q][k] — float4 along k, conflict-free.
            *reinterpret_cast<float4*>(&Ps[tr * 8 + i][tc * 4]) =
                make_float4(s[0], s[1], s[2], s[3]);
        }
        __syncthreads();   // GEMM1 KVs reads done + Ps visible

        // Load V tile natural: KVs[k][r]
        {
            #pragma unroll
            for (int it = 0; it < 8; it++) {
                const int kk = it * 8 + (t >> 4);
                const int r4 = (t & 15) * 4;
                *reinterpret_cast<float4*>(&KVs[kk][r4]) =
                    *reinterpret_cast<const float4*>(
                        &V[(size_t)(kv0 + kk) * RR + r4]);
            }
        }
        __syncthreads();

        // GEMM2: o2 += P * V, blocked 4 k-steps.
        // Ps reads are float4 row-broadcasts (all 16 lanes same address).
        #pragma unroll 2
        for (int kk4 = 0; kk4 < 64; kk4 += 4) {
            F4U2 bv0, bv1, bv2, bv3;
            bv0.f4 = *reinterpret_cast<const float4*>(&KVs[kk4 + 0][tc * 4]);
            bv1.f4 = *reinterpret_cast<const float4*>(&KVs[kk4 + 1][tc * 4]);
            bv2.f4 = *reinterpret_cast<const float4*>(&KVs[kk4 + 2][tc * 4]);
            bv3.f4 = *reinterpret_cast<const float4*>(&KVs[kk4 + 3][tc * 4]);
            #pragma unroll
            for (int i = 0; i < 8; i++) {
                float4 pa = *reinterpret_cast<const float4*>(
                    &Ps[tr * 8 + i][kk4]);
                uint64_t ap = bc2(pa.x);
                fma2(o2[i][0], ap, bv0.u2[0]); fma2(o2[i][1], ap, bv0.u2[1]);
                ap = bc2(pa.y);
                fma2(o2[i][0], ap, bv1.u2[0]); fma2(o2[i][1], ap, bv1.u2[1]);
                ap = bc2(pa.z);
                fma2(o2[i][0], ap, bv2.u2[0]); fma2(o2[i][1], ap, bv2.u2[1]);
                ap = bc2(pa.w);
                fma2(o2[i][0], ap, bv3.u2[0]); fma2(o2[i][1], ap, bv3.u2[1]);
            }
        }
    }

    // Epilogue: divide by l, store to g_vals in [b,h,s,r] order
    // (== the reference's raw (B,H,S,R)->(B,S,H*R) reshape).
    #pragma unroll
    for (int i = 0; i < 8; i++) {
        const uint64_t inv2 = bc2(1.0f / l[i]);
        mul2(o2[i][0], inv2);
        mul2(o2[i][1], inv2);
        float2 r0 = upk2(o2[i][0]), r1 = upk2(o2[i][1]);
        *reinterpret_cast<float4*>(
            &g_vals[(size_t)z * SS * RR +
                    (size_t)(s0 + tr * 8 + i) * RR + tc * 4]) =
            make_float4(r0.x, r0.y, r1.x, r1.y);
    }
}

// ---------------------------------------------------------------------------
// Kernel 3: out = g_vals (flat [4096 x 1024]) @ wo [1024 x 1024]
// ---------------------------------------------------------------------------
__global__ void __launch_bounds__(256) out_kernel(
    const float* __restrict__ W, float* __restrict__ C)
{
    __shared__ float As[8][128];
    __shared__ float Bs[8][128];

    const int t  = threadIdx.x;
    const int m0 = blockIdx.y * 128;
    const int n0 = blockIdx.x * 128;
    const int tr = t >> 4;
    const int tc = t & 15;
    const int aRow = t >> 1;
    const int aCol = (t & 1) * 4;
    const int bRow = t >> 5;
    const int bCol = (t & 31) * 4;

    uint64_t acc[8][4] = {};

    for (int k0 = 0; k0 < DD; k0 += 8) {
        float4 av = *reinterpret_cast<const float4*>(
            &g_vals[(size_t)(m0 + aRow) * DD + k0 + aCol]);
        As[aCol + 0][aRow] = av.x;
        As[aCol + 1][aRow] = av.y;
        As[aCol + 2][aRow] = av.z;
        As[aCol + 3][aRow] = av.w;

        float4 bv = *reinterpret_cast<const float4*>(
            &W[(size_t)(k0 + bRow) * DD + n0 + bCol]);
        *reinterpret_cast<float4*>(&Bs[bRow][bCol]) = bv;

        __syncthreads();
        #pragma unroll
        for (int kk = 0; kk < 8; kk++) {
            float4 ra0 = *reinterpret_cast<const float4*>(&As[kk][tr * 8]);
            float4 ra1 = *reinterpret_cast<const float4*>(&As[kk][tr * 8 + 4]);
            F4U2 rb0, rb1;
            rb0.f4 = *reinterpret_cast<const float4*>(&Bs[kk][tc * 8]);
            rb1.f4 = *reinterpret_cast<const float4*>(&Bs[kk][tc * 8 + 4]);
            uint64_t b2[4] = {rb0.u2[0], rb0.u2[1], rb1.u2[0], rb1.u2[1]};
            uint64_t a2[8] = {bc2(ra0.x), bc2(ra0.y), bc2(ra0.z), bc2(ra0.w),
                              bc2(ra1.x), bc2(ra1.y), bc2(ra1.z), bc2(ra1.w)};
            #pragma unroll
            for (int i = 0; i < 8; i++)
                #pragma unroll
                for (int j = 0; j < 4; j++)
                    fma2(acc[i][j], a2[i], b2[j]);
        }
        __syncthreads();
    }

    #pragma unroll
    for (int i = 0; i < 8; i++) {
        float* dst = &C[(size_t)(m0 + tr * 8 + i) * DD + n0 + tc * 8];
        float2 c0 = upk2(acc[i][0]), c1 = upk2(acc[i][1]);
        float2 c2 = upk2(acc[i][2]), c3 = upk2(acc[i][3]);
        *reinterpret_cast<float4*>(dst)     = make_float4(c0.x, c0.y, c1.x, c1.y);
        *reinterpret_cast<float4*>(dst + 4) = make_float4(c2.x, c2.y, c3.x, c3.y);
    }
}

// ---------------------------------------------------------------------------
// Launch
// ---------------------------------------------------------------------------
extern "C" void kernel_launch(void* const* d_in, const int* in_sizes, int n_in,
                              void* d_out, int out_size)
{
    const float* q  = (const float*)d_in[0];
    const float* k  = (const float*)d_in[1];
    const float* v  = (const float*)d_in[2];
    const float* wq = (const float*)d_in[3];
    const float* wk = (const float*)d_in[4];
    const float* wv = (const float*)d_in[5];
    const float* wo = (const float*)d_in[6];
    float* out = (float*)d_out;

    (void)in_sizes; (void)n_in; (void)out_size;

    // 1) QKV projections
    dim3 g1(DD / 128, (BB * SS) / 128, 3);
    proj_kernel<<<g1, 256>>>(q, k, v, wq, wk, wv);

    // 2) fused attention (QK^T + softmax + AV), one CTA per 64-row Q tile
    dim3 g2(SS / 64, BH);
    attn_kernel<<<g2, 128>>>();

    // 3) output projection
    dim3 g3(DD / 128, (BB * SS) / 128, 1);
    out_kernel<<<g3, 256>>>(wo, out);
}

// round 7
// speedup vs baseline: 1.4514x; 1.4514x over previous
#include <cuda_runtime.h>
#include <cuda_bf16.h>
#include <cstdint>

// ---------------------------------------------------------------------------
// Problem constants
// ---------------------------------------------------------------------------
#define BB 2
#define SS 2048
#define DD 1024
#define HH 16
#define RR 64
#define BH (BB * HH)   // 32
#define NEL (BB * SS * DD)

// ---------------------------------------------------------------------------
// Packed fp32x2 helpers (flash attention kernel)
// ---------------------------------------------------------------------------
__device__ __forceinline__ uint64_t pk2(float lo, float hi) {
    uint64_t r;
    asm("mov.b64 %0, {%1, %2};" : "=l"(r)
        : "r"(__float_as_uint(lo)), "r"(__float_as_uint(hi)));
    return r;
}
__device__ __forceinline__ uint64_t bc2(float v) { return pk2(v, v); }
__device__ __forceinline__ float2 upk2(uint64_t v) {
    uint32_t lo, hi;
    asm("mov.b64 {%0, %1}, %2;" : "=r"(lo), "=r"(hi) : "l"(v));
    return make_float2(__uint_as_float(lo), __uint_as_float(hi));
}
__device__ __forceinline__ void fma2(uint64_t& d, uint64_t a, uint64_t b) {
    asm("fma.rn.f32x2 %0, %1, %2, %0;" : "+l"(d) : "l"(a), "l"(b));
}
__device__ __forceinline__ void mul2(uint64_t& d, uint64_t a) {
    asm("mul.rn.f32x2 %0, %0, %1;" : "+l"(d) : "l"(a));
}
union F4U2 { float4 f4; uint64_t u2[2]; };

// ---------------------------------------------------------------------------
// mma.sync helpers (baseline PTX, works on plain sm_100 target)
// ---------------------------------------------------------------------------
__device__ __forceinline__ uint32_t smem_u32(const void* p) {
    uint32_t a;
    asm("{ .reg .u64 t; cvta.to.shared.u64 t, %1; cvt.u32.u64 %0, t; }"
        : "=r"(a) : "l"(p));
    return a;
}
__device__ __forceinline__ void ldm_x4(uint32_t* r, uint32_t addr) {
    asm volatile("ldmatrix.sync.aligned.m8n8.x4.shared.b16 {%0,%1,%2,%3}, [%4];"
                 : "=r"(r[0]), "=r"(r[1]), "=r"(r[2]), "=r"(r[3]) : "r"(addr));
}
__device__ __forceinline__ void mma_bf16(float* c, const uint32_t* a,
                                         const uint32_t* b) {
    asm volatile(
        "mma.sync.aligned.m16n8k16.row.col.f32.bf16.bf16.f32 "
        "{%0,%1,%2,%3}, {%4,%5,%6,%7}, {%8,%9}, {%0,%1,%2,%3};"
        : "+f"(c[0]), "+f"(c[1]), "+f"(c[2]), "+f"(c[3])
        : "r"(a[0]), "r"(a[1]), "r"(a[2]), "r"(a[3]), "r"(b[0]), "r"(b[1]));
}
__device__ __forceinline__ void cp16(uint32_t dst, const void* src) {
    asm volatile("cp.async.cg.shared.global [%0], [%1], 16;"
                 :: "r"(dst), "l"(__cvta_generic_to_global(src)));
}
#define CP_COMMIT() asm volatile("cp.async.commit_group;" ::: "memory")
#define CP_WAIT0()  asm volatile("cp.async.wait_group 0;" ::: "memory")

__device__ __forceinline__ uint32_t swz(uint32_t o) { return o ^ ((o >> 3) & 0x70); }

// ---------------------------------------------------------------------------
// Scratch
// ---------------------------------------------------------------------------
__device__ float g_Q[BH * SS * RR];
__device__ float g_K[BH * SS * RR];
__device__ float g_V[BH * SS * RR];
__device__ float g_vals[NEL];

// 2-way bf16 splits: activations [m][k], weights transposed to [n][k]
__device__ __nv_bfloat16 g_qs[2][NEL];
__device__ __nv_bfloat16 g_ks[2][NEL];
__device__ __nv_bfloat16 g_vs[2][NEL];
__device__ __nv_bfloat16 g_os[2][NEL];
__device__ __nv_bfloat16 g_wqT[2][DD * DD];
__device__ __nv_bfloat16 g_wkT[2][DD * DD];
__device__ __nv_bfloat16 g_wvT[2][DD * DD];
__device__ __nv_bfloat16 g_woT[2][DD * DD];

// ---------------------------------------------------------------------------
// fp32 -> 2-way bf16 split converters
// ---------------------------------------------------------------------------
__global__ void __launch_bounds__(256) conv_rows_kernel(
    const float* __restrict__ src_host, int sel)
{
    const float* src = (sel == 3) ? g_vals : src_host;
    __nv_bfloat16 *d0, *d1;
    if (sel == 0)      { d0 = g_qs[0]; d1 = g_qs[1]; }
    else if (sel == 1) { d0 = g_ks[0]; d1 = g_ks[1]; }
    else if (sel == 2) { d0 = g_vs[0]; d1 = g_vs[1]; }
    else               { d0 = g_os[0]; d1 = g_os[1]; }

    for (int i = blockIdx.x * blockDim.x + threadIdx.x; i < NEL;
         i += gridDim.x * blockDim.x) {
        float x = src[i];
        __nv_bfloat16 b0 = __float2bfloat16(x);
        d0[i] = b0;
        d1[i] = __float2bfloat16(x - __bfloat162float(b0));
    }
}

// Weight transpose + split. sel 0..2: [h][d][r] -> [n=h*64+r][d]; 3: wo [k][n]->[n][k]
__global__ void __launch_bounds__(256) conv_w_kernel(
    const float* __restrict__ wq, const float* __restrict__ wk,
    const float* __restrict__ wv, const float* __restrict__ wo)
{
    const int sel = blockIdx.z;
    const float* W = (sel == 0) ? wq : (sel == 1) ? wk : (sel == 2) ? wv : wo;
    __nv_bfloat16 *d0, *d1;
    if (sel == 0)      { d0 = g_wqT[0]; d1 = g_wqT[1]; }
    else if (sel == 1) { d0 = g_wkT[0]; d1 = g_wkT[1]; }
    else if (sel == 2) { d0 = g_wvT[0]; d1 = g_wvT[1]; }
    else               { d0 = g_woT[0]; d1 = g_woT[1]; }

    __shared__ float tile[32][33];
    const int tx = threadIdx.x & 31;
    const int ty = threadIdx.x >> 5;
    const int ct = blockIdx.x;
    const int rt = blockIdx.y;

    #pragma unroll
    for (int i = 0; i < 4; i++) {
        const int d = rt * 32 + ty + i * 8;
        const int n = ct * 32 + tx;
        size_t idx;
        if (sel < 3) idx = ((size_t)(n >> 6) * DD + d) * RR + (n & 63);
        else         idx = (size_t)d * DD + n;
        tile[ty + i * 8][tx] = W[idx];
    }
    __syncthreads();
    #pragma unroll
    for (int i = 0; i < 4; i++) {
        const int nl = ty + i * 8;
        const int n  = ct * 32 + nl;
        const int d  = rt * 32 + tx;
        float x = tile[tx][nl];
        __nv_bfloat16 b0 = __float2bfloat16(x);
        size_t o = (size_t)n * DD + d;
        d0[o] = b0;
        d1[o] = __float2bfloat16(x - __bfloat162float(b0));
    }
}

// ---------------------------------------------------------------------------
// mma.sync split-bf16 GEMM.
//   C[m][n] = sum_t A_{ti[t]}[m][k] * B_{tj[t]}[n][k]  (terms folded into K)
//   CTA tile 128x128, 8 warps (2m x 4n), warp tile 64x32, K-stage 64,
//   cp.async double-buffered smem (2 x 32KB), SW128 swizzle + ldmatrix.
//   kinds 0/1 (Q/K): 4 terms.  kinds 2/3 (V/out): 3 terms.
// ---------------------------------------------------------------------------
#define GEMM_SMEM 65536

__global__ void __launch_bounds__(256) gemm_kernel(float* __restrict__ outC,
                                                   int kind_base)
{
    const int kind = kind_base + blockIdx.z;
    const __nv_bfloat16 *Ax[2], *Bx[2];
    float* C;
    int nterms;
    if (kind == 0)      { Ax[0] = g_qs[0]; Ax[1] = g_qs[1];
                          Bx[0] = g_wqT[0]; Bx[1] = g_wqT[1];
                          C = g_Q; nterms = 4; }
    else if (kind == 1) { Ax[0] = g_ks[0]; Ax[1] = g_ks[1];
                          Bx[0] = g_wkT[0]; Bx[1] = g_wkT[1];
                          C = g_K; nterms = 4; }
    else if (kind == 2) { Ax[0] = g_vs[0]; Ax[1] = g_vs[1];
                          Bx[0] = g_wvT[0]; Bx[1] = g_wvT[1];
                          C = g_V; nterms = 3; }
    else                { Ax[0] = g_os[0]; Ax[1] = g_os[1];
                          Bx[0] = g_woT[0]; Bx[1] = g_woT[1];
                          C = outC; nterms = 3; }
    // term schedule: (i,j) pairs; 16 stages of K=64 per term
    const int ti[4] = {0, 0, 1, 1};
    const int tj[4] = {0, 1, 0, 1};
    const int NST = nterms * 16;

    extern __shared__ char smem[];
    const uint32_t sb = smem_u32(smem);
    const int t      = threadIdx.x;
    const int lane   = t & 31;
    const int wid    = t >> 5;
    const int warp_m = wid >> 2;          // 0..1
    const int warp_n = wid & 3;           // 0..3
    const int m0 = blockIdx.y * 128;
    const int n0 = blockIdx.x * 128;

    float acc[4][4][4];
    #pragma unroll
    for (int a = 0; a < 4; a++)
        #pragma unroll
        for (int b = 0; b < 4; b++)
            #pragma unroll
            for (int c = 0; c < 4; c++) acc[a][b][c] = 0.f;

    // per-thread load coords (16B chunks; 8 per thread per stage)
    const int lrow = t >> 1;              // 0..127 (used twice: A then B halves)
    // each thread loads 4 A chunks + 4 B chunks:
    //   chunk id = it*256 + t  -> row = cid>>3, col16 = cid&7

    // ldmatrix per-lane addressing (precomputed offsets)
    const int a_row  = warp_m * 64 + (lane & 15);
    const int a_koff = (lane >> 4) * 16;            // bytes
    const int b_row  = warp_n * 32 + (lane & 7) + ((lane >> 4) & 1) * 8;
    const int b_koff = ((lane >> 3) & 1) * 16;      // bytes
    (void)lrow;

    // prologue: stage 0
    {
        const int tt = 0, k0 = 0;
        const __nv_bfloat16* Ag = Ax[ti[tt]];
        const __nv_bfloat16* Bg = Bx[tj[tt]];
        const uint32_t abase = sb, bbase = sb + 16384;
        #pragma unroll
        for (int it = 0; it < 4; it++) {
            const int cid = it * 256 + t;
            const int row = cid >> 3, c16 = cid & 7;
            cp16(abase + swz(row * 128 + c16 * 16),
                 Ag + (size_t)(m0 + row) * DD + k0 + c16 * 8);
            cp16(bbase + swz(row * 128 + c16 * 16),
                 Bg + (size_t)(n0 + row) * DD + k0 + c16 * 8);
        }
        CP_COMMIT();
    }

    for (int s = 0; s < NST; s++) {
        CP_WAIT0();
        __syncthreads();
        if (s + 1 < NST) {
            const int sn = s + 1;
            const int tt = sn >> 4;
            const int k0 = (sn & 15) * 64;
            const __nv_bfloat16* Ag = Ax[ti[tt]];
            const __nv_bfloat16* Bg = Bx[tj[tt]];
            const uint32_t abase = sb + (sn & 1) * 32768;
            const uint32_t bbase = abase + 16384;
            #pragma unroll
            for (int it = 0; it < 4; it++) {
                const int cid = it * 256 + t;
                const int row = cid >> 3, c16 = cid & 7;
                cp16(abase + swz(row * 128 + c16 * 16),
                     Ag + (size_t)(m0 + row) * DD + k0 + c16 * 8);
                cp16(bbase + swz(row * 128 + c16 * 16),
                     Bg + (size_t)(n0 + row) * DD + k0 + c16 * 8);
            }
            CP_COMMIT();
        }
        // compute this stage
        const uint32_t abase = sb + (s & 1) * 32768;
        const uint32_t bbase = abase + 16384;
        #pragma unroll
        for (int k16 = 0; k16 < 64; k16 += 16) {
            uint32_t ar[4][4], br[4][2];
            #pragma unroll
            for (int mi = 0; mi < 4; mi++) {
                const int row = a_row + mi * 16;
                ldm_x4(ar[mi], abase + swz(row * 128 + k16 * 2 + a_koff));
            }
            #pragma unroll
            for (int nb = 0; nb < 2; nb++) {
                const int n = b_row + nb * 16;
                uint32_t r[4];
                ldm_x4(r, bbase + swz(n * 128 + k16 * 2 + b_koff));
                br[nb * 2][0] = r[0]; br[nb * 2][1] = r[1];
                br[nb * 2 + 1][0] = r[2]; br[nb * 2 + 1][1] = r[3];
            }
            #pragma unroll
            for (int mi = 0; mi < 4; mi++)
                #pragma unroll
                for (int ni = 0; ni < 4; ni++)
                    mma_bf16(acc[mi][ni], ar[mi], br[ni]);
        }
    }

    // epilogue
    #pragma unroll
    for (int mi = 0; mi < 4; mi++) {
        #pragma unroll
        for (int ni = 0; ni < 4; ni++) {
            const int r0 = m0 + warp_m * 64 + mi * 16 + (lane >> 2);
            const int c  = n0 + warp_n * 32 + ni * 8 + (lane & 3) * 2;
            #pragma unroll
            for (int half = 0; half < 2; half++) {
                const int m = r0 + half * 8;
                float2 v = make_float2(acc[mi][ni][half * 2],
                                       acc[mi][ni][half * 2 + 1]);
                if (kind < 3) {
                    const int h = c >> 6, r = c & 63;
                    const int b = m >> 11, sl = m & 2047;
                    *reinterpret_cast<float2*>(
                        &C[(((size_t)b * HH + h) * SS + sl) * RR + r]) = v;
                } else {
                    *reinterpret_cast<float2*>(&C[(size_t)m * DD + c]) = v;
                }
            }
        }
    }
}

// ---------------------------------------------------------------------------
// Fused flash attention per (b,h) — unchanged from the 1792us passing kernel.
// ---------------------------------------------------------------------------
__global__ void __launch_bounds__(128) attn_kernel()
{
    const int z  = blockIdx.y;
    const int s0 = blockIdx.x * 64;
    const float* Q = g_Q + (size_t)z * SS * RR;
    const float* K = g_K + (size_t)z * SS * RR;
    const float* V = g_V + (size_t)z * SS * RR;

    __shared__ float Qs[64][64];
    __shared__ float KVs[64][64];
    __shared__ float Ps[64][64];

    const int t  = threadIdx.x;
    const int tr = t >> 4;
    const int tc = t & 15;

    {
        const int row = t >> 1;
        const int rb  = (t & 1) * 4;
        #pragma unroll
        for (int it = 0; it < 8; it++) {
            const int r0 = it * 8 + rb;
            float4 v4 = *reinterpret_cast<const float4*>(
                &Q[(size_t)(s0 + row) * RR + r0]);
            Qs[r0 + 0][row] = v4.x * 0.125f;
            Qs[r0 + 1][row] = v4.y * 0.125f;
            Qs[r0 + 2][row] = v4.z * 0.125f;
            Qs[r0 + 3][row] = v4.w * 0.125f;
        }
    }

    float m[8], l[8];
    uint64_t o2[8][2];
    #pragma unroll
    for (int i = 0; i < 8; i++) {
        m[i] = -3.0e38f; l[i] = 0.f;
        o2[i][0] = 0; o2[i][1] = 0;
    }

    for (int kv0 = 0; kv0 < SS; kv0 += 64) {
        __syncthreads();
        {
            const int row = t >> 1;
            const int rb  = (t & 1) * 4;
            #pragma unroll
            for (int it = 0; it < 8; it++) {
                const int r0 = it * 8 + rb;
                float4 v4 = *reinterpret_cast<const float4*>(
                    &K[(size_t)(kv0 + row) * RR + r0]);
                KVs[r0 + 0][row] = v4.x;
                KVs[r0 + 1][row] = v4.y;
                KVs[r0 + 2][row] = v4.z;
                KVs[r0 + 3][row] = v4.w;
            }
        }
        __syncthreads();

        uint64_t s2[8][2] = {};
        #pragma unroll 4
        for (int r = 0; r < 64; r++) {
            float4 a0 = *reinterpret_cast<const float4*>(&Qs[r][tr * 8]);
            float4 a1 = *reinterpret_cast<const float4*>(&Qs[r][tr * 8 + 4]);
            F4U2 b; b.f4 = *reinterpret_cast<const float4*>(&KVs[r][tc * 4]);
            uint64_t a2[8] = {bc2(a0.x), bc2(a0.y), bc2(a0.z), bc2(a0.w),
                              bc2(a1.x), bc2(a1.y), bc2(a1.z), bc2(a1.w)};
            #pragma unroll
            for (int i = 0; i < 8; i++) {
                fma2(s2[i][0], a2[i], b.u2[0]);
                fma2(s2[i][1], a2[i], b.u2[1]);
            }
        }

        #pragma unroll
        for (int i = 0; i < 8; i++) {
            float2 p0 = upk2(s2[i][0]), p1 = upk2(s2[i][1]);
            float s[4] = {p0.x, p0.y, p1.x, p1.y};
            float mt = fmaxf(fmaxf(s[0], s[1]), fmaxf(s[2], s[3]));
            #pragma unroll
            for (int off = 1; off < 16; off <<= 1)
                mt = fmaxf(mt, __shfl_xor_sync(0xffffffffu, mt, off));
            const float mn    = fmaxf(m[i], mt);
            const float alpha = __expf(m[i] - mn);
            m[i] = mn;
            float rs = 0.f;
            #pragma unroll
            for (int j = 0; j < 4; j++) {
                s[j] = __expf(s[j] - mn);
                rs += s[j];
            }
            #pragma unroll
            for (int off = 1; off < 16; off <<= 1)
                rs += __shfl_xor_sync(0xffffffffu, rs, off);
            l[i] = l[i] * alpha + rs;
            const uint64_t al2 = bc2(alpha);
            mul2(o2[i][0], al2);
            mul2(o2[i][1], al2);
            *reinterpret_cast<float4*>(&Ps[tr * 8 + i][tc * 4]) =
                make_float4(s[0], s[1], s[2], s[3]);
        }
        __syncthreads();

        {
            #pragma unroll
            for (int it = 0; it < 8; it++) {
                const int kk = it * 8 + (t >> 4);
                const int r4 = (t & 15) * 4;
                *reinterpret_cast<float4*>(&KVs[kk][r4]) =
                    *reinterpret_cast<const float4*>(
                        &V[(size_t)(kv0 + kk) * RR + r4]);
            }
        }
        __syncthreads();

        #pragma unroll 2
        for (int kk4 = 0; kk4 < 64; kk4 += 4) {
            F4U2 bv0, bv1, bv2, bv3;
            bv0.f4 = *reinterpret_cast<const float4*>(&KVs[kk4 + 0][tc * 4]);
            bv1.f4 = *reinterpret_cast<const float4*>(&KVs[kk4 + 1][tc * 4]);
            bv2.f4 = *reinterpret_cast<const float4*>(&KVs[kk4 + 2][tc * 4]);
            bv3.f4 = *reinterpret_cast<const float4*>(&KVs[kk4 + 3][tc * 4]);
            #pragma unroll
            for (int i = 0; i < 8; i++) {
                float4 pa = *reinterpret_cast<const float4*>(
                    &Ps[tr * 8 + i][kk4]);
                uint64_t ap = bc2(pa.x);
                fma2(o2[i][0], ap, bv0.u2[0]); fma2(o2[i][1], ap, bv0.u2[1]);
                ap = bc2(pa.y);
                fma2(o2[i][0], ap, bv1.u2[0]); fma2(o2[i][1], ap, bv1.u2[1]);
                ap = bc2(pa.z);
                fma2(o2[i][0], ap, bv2.u2[0]); fma2(o2[i][1], ap, bv2.u2[1]);
                ap = bc2(pa.w);
                fma2(o2[i][0], ap, bv3.u2[0]); fma2(o2[i][1], ap, bv3.u2[1]);
            }
        }
    }

    #pragma unroll
    for (int i = 0; i < 8; i++) {
        const uint64_t inv2 = bc2(1.0f / l[i]);
        mul2(o2[i][0], inv2);
        mul2(o2[i][1], inv2);
        float2 r0 = upk2(o2[i][0]), r1 = upk2(o2[i][1]);
        *reinterpret_cast<float4*>(
            &g_vals[(size_t)z * SS * RR +
                    (size_t)(s0 + tr * 8 + i) * RR + tc * 4]) =
            make_float4(r0.x, r0.y, r1.x, r1.y);
    }
}

// ---------------------------------------------------------------------------
// Launch
// ---------------------------------------------------------------------------
extern "C" void kernel_launch(void* const* d_in, const int* in_sizes, int n_in,
                              void* d_out, int out_size)
{
    const float* q  = (const float*)d_in[0];
    const float* k  = (const float*)d_in[1];
    const float* v  = (const float*)d_in[2];
    const float* wq = (const float*)d_in[3];
    const float* wk = (const float*)d_in[4];
    const float* wv = (const float*)d_in[5];
    const float* wo = (const float*)d_in[6];
    float* out = (float*)d_out;

    (void)in_sizes; (void)n_in; (void)out_size;

    cudaFuncSetAttribute(gemm_kernel,
                         cudaFuncAttributeMaxDynamicSharedMemorySize, GEMM_SMEM);

    // 1) split inputs and weights to 2-way bf16
    conv_rows_kernel<<<2048, 256>>>(q, 0);
    conv_rows_kernel<<<2048, 256>>>(k, 1);
    conv_rows_kernel<<<2048, 256>>>(v, 2);
    conv_w_kernel<<<dim3(32, 32, 4), 256>>>(wq, wk, wv, wo);

    // 2) Q/K/V projections (mma.sync, kinds 0,1,2)
    gemm_kernel<<<dim3(8, 32, 3), 256, GEMM_SMEM>>>(nullptr, 0);

    // 3) fused attention (fp32 FFMA2 flash)
    attn_kernel<<<dim3(SS / 64, BH), 128>>>();

    // 4) split attention output (device-side g_vals), output projection
    conv_rows_kernel<<<2048, 256>>>(q /*ignored*/, 3);
    gemm_kernel<<<dim3(8, 32, 1), 256, GEMM_SMEM>>>(out, 3);
}

// round 8
// speedup vs baseline: 2.4451x; 1.6847x over previous
#include <cuda_runtime.h>
#include <cuda_bf16.h>
#include <cstdint>

// ---------------------------------------------------------------------------
// Problem constants
// ---------------------------------------------------------------------------
#define BB 2
#define SS 2048
#define DD 1024
#define HH 16
#define RR 64
#define BH (BB * HH)   // 32
#define NEL (BB * SS * DD)

// ---------------------------------------------------------------------------
// mma.sync helpers (baseline PTX, plain sm_100 target)
// ---------------------------------------------------------------------------
__device__ __forceinline__ uint32_t smem_u32(const void* p) {
    uint32_t a;
    asm("{ .reg .u64 t; cvta.to.shared.u64 t, %1; cvt.u32.u64 %0, t; }"
        : "=r"(a) : "l"(p));
    return a;
}
__device__ __forceinline__ void ldm_x4(uint32_t* r, uint32_t addr) {
    asm volatile("ldmatrix.sync.aligned.m8n8.x4.shared.b16 {%0,%1,%2,%3}, [%4];"
                 : "=r"(r[0]), "=r"(r[1]), "=r"(r[2]), "=r"(r[3]) : "r"(addr));
}
__device__ __forceinline__ void ldm_x4_t(uint32_t* r, uint32_t addr) {
    asm volatile("ldmatrix.sync.aligned.m8n8.x4.trans.shared.b16 {%0,%1,%2,%3}, [%4];"
                 : "=r"(r[0]), "=r"(r[1]), "=r"(r[2]), "=r"(r[3]) : "r"(addr));
}
__device__ __forceinline__ void mma_bf16(float* c, const uint32_t* a,
                                         const uint32_t* b) {
    asm volatile(
        "mma.sync.aligned.m16n8k16.row.col.f32.bf16.bf16.f32 "
        "{%0,%1,%2,%3}, {%4,%5,%6,%7}, {%8,%9}, {%0,%1,%2,%3};"
        : "+f"(c[0]), "+f"(c[1]), "+f"(c[2]), "+f"(c[3])
        : "r"(a[0]), "r"(a[1]), "r"(a[2]), "r"(a[3]), "r"(b[0]), "r"(b[1]));
}
__device__ __forceinline__ void cp16(uint32_t dst, const void* src) {
    asm volatile("cp.async.cg.shared.global [%0], [%1], 16;"
                 :: "r"(dst), "l"(__cvta_generic_to_global(src)));
}
#define CP_COMMIT() asm volatile("cp.async.commit_group;" ::: "memory")
#define CP_WAIT0()  asm volatile("cp.async.wait_group 0;" ::: "memory")
#define CP_WAIT1()  asm volatile("cp.async.wait_group 1;" ::: "memory")

__device__ __forceinline__ uint32_t swz(uint32_t o) { return o ^ ((o >> 3) & 0x70); }

// Split a float pair into bf16 hi/lo packed u32s.
__device__ __forceinline__ void splitpair(float x, float y,
                                          uint32_t& h, uint32_t& l) {
    __nv_bfloat16 hx = __float2bfloat16(x), hy = __float2bfloat16(y);
    __nv_bfloat16 lx = __float2bfloat16(x - __bfloat162float(hx));
    __nv_bfloat16 ly = __float2bfloat16(y - __bfloat162float(hy));
    __nv_bfloat162 H; H.x = hx; H.y = hy;
    __nv_bfloat162 L; L.x = lx; L.y = ly;
    h = *reinterpret_cast<uint32_t*>(&H);
    l = *reinterpret_cast<uint32_t*>(&L);
}

// ---------------------------------------------------------------------------
// Scratch
// ---------------------------------------------------------------------------
// input splits for proj GEMMs
__device__ __nv_bfloat16 g_qs[2][NEL];
__device__ __nv_bfloat16 g_ks[2][NEL];
__device__ __nv_bfloat16 g_vs[2][NEL];
__device__ __nv_bfloat16 g_os[2][NEL];          // attn output splits
__device__ __nv_bfloat16 g_wqT[2][DD * DD];
__device__ __nv_bfloat16 g_wkT[2][DD * DD];
__device__ __nv_bfloat16 g_wvT[2][DD * DD];
__device__ __nv_bfloat16 g_woT[2][DD * DD];
// projection outputs as bf16 hi/lo planes, [b,h,s,r] layout (Q pre-scaled)
__device__ __nv_bfloat16 g_Qb[2][BH * SS * RR];
__device__ __nv_bfloat16 g_Kb[2][BH * SS * RR];
__device__ __nv_bfloat16 g_Vb[2][BH * SS * RR];

// ---------------------------------------------------------------------------
// fp32 -> 2-way bf16 split converters (inputs + weights)
// ---------------------------------------------------------------------------
__global__ void __launch_bounds__(256) conv_rows_kernel(
    const float* __restrict__ src, int sel)
{
    __nv_bfloat16 *d0, *d1;
    if (sel == 0)      { d0 = g_qs[0]; d1 = g_qs[1]; }
    else if (sel == 1) { d0 = g_ks[0]; d1 = g_ks[1]; }
    else               { d0 = g_vs[0]; d1 = g_vs[1]; }

    for (int i = blockIdx.x * blockDim.x + threadIdx.x; i < NEL;
         i += gridDim.x * blockDim.x) {
        float x = src[i];
        __nv_bfloat16 b0 = __float2bfloat16(x);
        d0[i] = b0;
        d1[i] = __float2bfloat16(x - __bfloat162float(b0));
    }
}

__global__ void __launch_bounds__(256) conv_w_kernel(
    const float* __restrict__ wq, const float* __restrict__ wk,
    const float* __restrict__ wv, const float* __restrict__ wo)
{
    const int sel = blockIdx.z;
    const float* W = (sel == 0) ? wq : (sel == 1) ? wk : (sel == 2) ? wv : wo;
    __nv_bfloat16 *d0, *d1;
    if (sel == 0)      { d0 = g_wqT[0]; d1 = g_wqT[1]; }
    else if (sel == 1) { d0 = g_wkT[0]; d1 = g_wkT[1]; }
    else if (sel == 2) { d0 = g_wvT[0]; d1 = g_wvT[1]; }
    else               { d0 = g_woT[0]; d1 = g_woT[1]; }

    __shared__ float tile[32][33];
    const int tx = threadIdx.x & 31;
    const int ty = threadIdx.x >> 5;
    const int ct = blockIdx.x;
    const int rt = blockIdx.y;

    #pragma unroll
    for (int i = 0; i < 4; i++) {
        const int d = rt * 32 + ty + i * 8;
        const int n = ct * 32 + tx;
        size_t idx;
        if (sel < 3) idx = ((size_t)(n >> 6) * DD + d) * RR + (n & 63);
        else         idx = (size_t)d * DD + n;
        tile[ty + i * 8][tx] = W[idx];
    }
    __syncthreads();
    #pragma unroll
    for (int i = 0; i < 4; i++) {
        const int nl = ty + i * 8;
        const int n  = ct * 32 + nl;
        const int d  = rt * 32 + tx;
        float x = tile[tx][nl];
        __nv_bfloat16 b0 = __float2bfloat16(x);
        size_t o = (size_t)n * DD + d;
        d0[o] = b0;
        d1[o] = __float2bfloat16(x - __bfloat162float(b0));
    }
}

// ---------------------------------------------------------------------------
// mma.sync split-bf16 GEMM (same engine as the 1235us passing version).
//   kinds 0/1 (Q/K proj): 4 terms -> bf16 hi/lo planes (Q scaled by 0.125)
//   kind 2  (V proj):     3 terms -> bf16 hi/lo planes
//   kind 3  (out proj):   3 terms -> fp32 outC
// ---------------------------------------------------------------------------
#define GEMM_SMEM 65536

__global__ void __launch_bounds__(256) gemm_kernel(float* __restrict__ outC,
                                                   int kind_base)
{
    const int kind = kind_base + blockIdx.z;
    const __nv_bfloat16 *Ax[2], *Bx[2];
    __nv_bfloat16 *P0 = nullptr, *P1 = nullptr;
    float scale = 1.0f;
    int nterms;
    if (kind == 0)      { Ax[0] = g_qs[0]; Ax[1] = g_qs[1];
                          Bx[0] = g_wqT[0]; Bx[1] = g_wqT[1];
                          P0 = g_Qb[0]; P1 = g_Qb[1]; scale = 0.125f; nterms = 4; }
    else if (kind == 1) { Ax[0] = g_ks[0]; Ax[1] = g_ks[1];
                          Bx[0] = g_wkT[0]; Bx[1] = g_wkT[1];
                          P0 = g_Kb[0]; P1 = g_Kb[1]; nterms = 4; }
    else if (kind == 2) { Ax[0] = g_vs[0]; Ax[1] = g_vs[1];
                          Bx[0] = g_wvT[0]; Bx[1] = g_wvT[1];
                          P0 = g_Vb[0]; P1 = g_Vb[1]; nterms = 3; }
    else                { Ax[0] = g_os[0]; Ax[1] = g_os[1];
                          Bx[0] = g_woT[0]; Bx[1] = g_woT[1];
                          nterms = 3; }
    const int ti[4] = {0, 0, 1, 1};
    const int tj[4] = {0, 1, 0, 1};
    const int NST = nterms * 16;

    extern __shared__ char smem[];
    const uint32_t sb = smem_u32(smem);
    const int t      = threadIdx.x;
    const int lane   = t & 31;
    const int wid    = t >> 5;
    const int warp_m = wid >> 2;
    const int warp_n = wid & 3;
    const int m0 = blockIdx.y * 128;
    const int n0 = blockIdx.x * 128;

    float acc[4][4][4];
    #pragma unroll
    for (int a = 0; a < 4; a++)
        #pragma unroll
        for (int b = 0; b < 4; b++)
            #pragma unroll
            for (int c = 0; c < 4; c++) acc[a][b][c] = 0.f;

    const int a_row  = warp_m * 64 + (lane & 15);
    const int a_koff = (lane >> 4) * 16;
    const int b_row  = warp_n * 32 + (lane & 7) + ((lane >> 4) & 1) * 8;
    const int b_koff = ((lane >> 3) & 1) * 16;

    {
        const __nv_bfloat16* Ag = Ax[0];
        const __nv_bfloat16* Bg = Bx[0];
        const uint32_t abase = sb, bbase = sb + 16384;
        #pragma unroll
        for (int it = 0; it < 4; it++) {
            const int cid = it * 256 + t;
            const int row = cid >> 3, c16 = cid & 7;
            cp16(abase + swz(row * 128 + c16 * 16),
                 Ag + (size_t)(m0 + row) * DD + c16 * 8);
            cp16(bbase + swz(row * 128 + c16 * 16),
                 Bg + (size_t)(n0 + row) * DD + c16 * 8);
        }
        CP_COMMIT();
    }

    for (int s = 0; s < NST; s++) {
        CP_WAIT0();
        __syncthreads();
        if (s + 1 < NST) {
            const int sn = s + 1;
            const int tt = sn >> 4;
            const int k0 = (sn & 15) * 64;
            const __nv_bfloat16* Ag = Ax[ti[tt]];
            const __nv_bfloat16* Bg = Bx[tj[tt]];
            const uint32_t abase = sb + (sn & 1) * 32768;
            const uint32_t bbase = abase + 16384;
            #pragma unroll
            for (int it = 0; it < 4; it++) {
                const int cid = it * 256 + t;
                const int row = cid >> 3, c16 = cid & 7;
                cp16(abase + swz(row * 128 + c16 * 16),
                     Ag + (size_t)(m0 + row) * DD + k0 + c16 * 8);
                cp16(bbase + swz(row * 128 + c16 * 16),
                     Bg + (size_t)(n0 + row) * DD + k0 + c16 * 8);
            }
            CP_COMMIT();
        }
        const uint32_t abase = sb + (s & 1) * 32768;
        const uint32_t bbase = abase + 16384;
        #pragma unroll
        for (int k16 = 0; k16 < 64; k16 += 16) {
            uint32_t ar[4][4], br[4][2];
            #pragma unroll
            for (int mi = 0; mi < 4; mi++) {
                const int row = a_row + mi * 16;
                ldm_x4(ar[mi], abase + swz(row * 128 + k16 * 2 + a_koff));
            }
            #pragma unroll
            for (int nb = 0; nb < 2; nb++) {
                const int n = b_row + nb * 16;
                uint32_t r[4];
                ldm_x4(r, bbase + swz(n * 128 + k16 * 2 + b_koff));
                br[nb * 2][0] = r[0]; br[nb * 2][1] = r[1];
                br[nb * 2 + 1][0] = r[2]; br[nb * 2 + 1][1] = r[3];
            }
            #pragma unroll
            for (int mi = 0; mi < 4; mi++)
                #pragma unroll
                for (int ni = 0; ni < 4; ni++)
                    mma_bf16(acc[mi][ni], ar[mi], br[ni]);
        }
    }

    // epilogue
    #pragma unroll
    for (int mi = 0; mi < 4; mi++) {
        #pragma unroll
        for (int ni = 0; ni < 4; ni++) {
            const int r0 = m0 + warp_m * 64 + mi * 16 + (lane >> 2);
            const int c  = n0 + warp_n * 32 + ni * 8 + (lane & 3) * 2;
            #pragma unroll
            for (int half = 0; half < 2; half++) {
                const int m = r0 + half * 8;
                float v0 = acc[mi][ni][half * 2] * scale;
                float v1 = acc[mi][ni][half * 2 + 1] * scale;
                if (kind < 3) {
                    const int h = c >> 6, r = c & 63;
                    const int b = m >> 11, sl = m & 2047;
                    size_t idx = (((size_t)b * HH + h) * SS + sl) * RR + r;
                    uint32_t hh, ll;
                    splitpair(v0, v1, hh, ll);
                    *reinterpret_cast<uint32_t*>(&P0[idx]) = hh;
                    *reinterpret_cast<uint32_t*>(&P1[idx]) = ll;
                } else {
                    *reinterpret_cast<float2*>(&outC[(size_t)m * DD + c]) =
                        make_float2(v0, v1);
                }
            }
        }
    }
}

// ---------------------------------------------------------------------------
// Tensor-core flash attention.
//   CTA = 128 q-rows of one (b,h); 8 warps, each owns a 16-row band.
//   KV tiles of 64, cp.async double-buffered bf16 hi/lo planes.
//   S = QK^T with 4 split terms (exact product of stored splits);
//   online softmax in mma fragment layout (quad shuffles);
//   P repacked in registers into A fragments (hi/lo), PV with 3 terms;
//   V B-fragments via ldmatrix.x4.trans from natural [t][r] layout.
// ---------------------------------------------------------------------------
#define ATT_SMEM 98304

__global__ void __launch_bounds__(256, 2) attn_kernel()
{
    const int z  = blockIdx.y;
    const int s0 = blockIdx.x * 128;
    extern __shared__ char sm[];
    const uint32_t sb = smem_u32(sm);
    const int t = threadIdx.x, lane = t & 31, wid = t >> 5;
    const size_t zoff = (size_t)z * SS * RR;

    // smem map: Q planes 2x16KB @0; per-buf K 2x8KB, V 2x8KB @32768+buf*32768
    #define QOFF(p)      (sb + (p) * 16384u)
    #define KOFF(bf, p)  (sb + 32768u + (bf) * 32768u + (p) * 8192u)
    #define VOFF(bf, p)  (sb + 32768u + (bf) * 32768u + 16384u + (p) * 8192u)

    // prologue: Q tile + KV tile 0
    #pragma unroll
    for (int p = 0; p < 2; p++) {
        const __nv_bfloat16* src = g_Qb[p] + zoff + (size_t)s0 * RR;
        #pragma unroll
        for (int it = 0; it < 4; it++) {
            const int cid = it * 256 + t;
            const int row = cid >> 3, c16 = cid & 7;
            cp16(QOFF(p) + swz(row * 128 + c16 * 16), src + row * 64 + c16 * 8);
        }
    }
    #pragma unroll
    for (int p = 0; p < 2; p++) {
        #pragma unroll
        for (int it = 0; it < 2; it++) {
            const int cid = it * 256 + t;
            const int row = cid >> 3, c16 = cid & 7;
            cp16(KOFF(0, p) + swz(row * 128 + c16 * 16),
                 g_Kb[p] + zoff + (size_t)row * RR + c16 * 8);
            cp16(VOFF(0, p) + swz(row * 128 + c16 * 16),
                 g_Vb[p] + zoff + (size_t)row * RR + c16 * 8);
        }
    }
    CP_COMMIT();

    float m0r = -3.0e38f, m1r = -3.0e38f, l0r = 0.f, l1r = 0.f;
    float oa[8][4];
    #pragma unroll
    for (int b = 0; b < 8; b++)
        #pragma unroll
        for (int c = 0; c < 4; c++) oa[b][c] = 0.f;

    for (int s = 0; s < 32; s++) {
        const int buf = s & 1;
        if (s + 1 < 32) {
            const int nb = (s + 1) & 1;
            const int kv = (s + 1) * 64;
            #pragma unroll
            for (int p = 0; p < 2; p++) {
                #pragma unroll
                for (int it = 0; it < 2; it++) {
                    const int cid = it * 256 + t;
                    const int row = cid >> 3, c16 = cid & 7;
                    cp16(KOFF(nb, p) + swz(row * 128 + c16 * 16),
                         g_Kb[p] + zoff + (size_t)(kv + row) * RR + c16 * 8);
                    cp16(VOFF(nb, p) + swz(row * 128 + c16 * 16),
                         g_Vb[p] + zoff + (size_t)(kv + row) * RR + c16 * 8);
                }
            }
            CP_COMMIT();
            CP_WAIT1();
        } else {
            CP_WAIT0();
        }
        __syncthreads();

        // ---- GEMM1: S = Q K^T (4 split terms = exact) ----
        float sa[8][4];
        #pragma unroll
        for (int b = 0; b < 8; b++)
            #pragma unroll
            for (int c = 0; c < 4; c++) sa[b][c] = 0.f;

        #pragma unroll
        for (int kb = 0; kb < 4; kb++) {
            uint32_t aq[2][4];
            const int arow = wid * 16 + (lane & 15);
            const int akoff = kb * 32 + (lane >> 4) * 16;
            #pragma unroll
            for (int p = 0; p < 2; p++)
                ldm_x4(aq[p], QOFF(p) + swz(arow * 128 + akoff));
            #pragma unroll
            for (int g = 0; g < 4; g++) {
                uint32_t bk[2][4];
                const int brow = g * 16 + (lane & 7) + ((lane >> 4) & 1) * 8;
                const int bkoff = kb * 32 + ((lane >> 3) & 1) * 16;
                #pragma unroll
                for (int p = 0; p < 2; p++)
                    ldm_x4(bk[p], KOFF(buf, p) + swz(brow * 128 + bkoff));
                #pragma unroll
                for (int pa = 0; pa < 2; pa++)
                    #pragma unroll
                    for (int pb = 0; pb < 2; pb++) {
                        mma_bf16(sa[2 * g],     aq[pa], &bk[pb][0]);
                        mma_bf16(sa[2 * g + 1], aq[pa], &bk[pb][2]);
                    }
            }
        }

        // ---- online softmax (rows lane>>2 and +8; quads share rows) ----
        float mt0 = -3.0e38f, mt1 = -3.0e38f;
        #pragma unroll
        for (int b = 0; b < 8; b++) {
            mt0 = fmaxf(mt0, fmaxf(sa[b][0], sa[b][1]));
            mt1 = fmaxf(mt1, fmaxf(sa[b][2], sa[b][3]));
        }
        mt0 = fmaxf(mt0, __shfl_xor_sync(0xffffffffu, mt0, 1));
        mt0 = fmaxf(mt0, __shfl_xor_sync(0xffffffffu, mt0, 2));
        mt1 = fmaxf(mt1, __shfl_xor_sync(0xffffffffu, mt1, 1));
        mt1 = fmaxf(mt1, __shfl_xor_sync(0xffffffffu, mt1, 2));
        const float mn0 = fmaxf(m0r, mt0), mn1 = fmaxf(m1r, mt1);
        const float al0 = __expf(m0r - mn0), al1 = __expf(m1r - mn1);
        m0r = mn0; m1r = mn1;
        float rs0 = 0.f, rs1 = 0.f;
        #pragma unroll
        for (int b = 0; b < 8; b++) {
            sa[b][0] = __expf(sa[b][0] - mn0);
            sa[b][1] = __expf(sa[b][1] - mn0);
            sa[b][2] = __expf(sa[b][2] - mn1);
            sa[b][3] = __expf(sa[b][3] - mn1);
            rs0 += sa[b][0] + sa[b][1];
            rs1 += sa[b][2] + sa[b][3];
        }
        rs0 += __shfl_xor_sync(0xffffffffu, rs0, 1);
        rs0 += __shfl_xor_sync(0xffffffffu, rs0, 2);
        rs1 += __shfl_xor_sync(0xffffffffu, rs1, 1);
        rs1 += __shfl_xor_sync(0xffffffffu, rs1, 2);
        l0r = l0r * al0 + rs0;
        l1r = l1r * al1 + rs1;
        #pragma unroll
        for (int b = 0; b < 8; b++) {
            oa[b][0] *= al0; oa[b][1] *= al0;
            oa[b][2] *= al1; oa[b][3] *= al1;
        }

        // ---- GEMM2: O += P V (3 split terms) ----
        #pragma unroll
        for (int kb = 0; kb < 4; kb++) {
            // repack S fragments (blocks 2kb, 2kb+1) into A fragments hi/lo
            uint32_t ph[4], pl[4];
            splitpair(sa[2 * kb][0],     sa[2 * kb][1],     ph[0], pl[0]);
            splitpair(sa[2 * kb][2],     sa[2 * kb][3],     ph[1], pl[1]);
            splitpair(sa[2 * kb + 1][0], sa[2 * kb + 1][1], ph[2], pl[2]);
            splitpair(sa[2 * kb + 1][2], sa[2 * kb + 1][3], ph[3], pl[3]);
            #pragma unroll
            for (int g = 0; g < 4; g++) {
                uint32_t bv[2][4];
                const int trow = kb * 16 + (lane & 7) + ((lane >> 3) & 1) * 8;
                const int rbyte = g * 32 + ((lane >> 4) & 1) * 16;
                #pragma unroll
                for (int p = 0; p < 2; p++)
                    ldm_x4_t(bv[p], VOFF(buf, p) + swz(trow * 128 + rbyte));
                mma_bf16(oa[2 * g], ph, &bv[0][0]);
                mma_bf16(oa[2 * g], ph, &bv[1][0]);
                mma_bf16(oa[2 * g], pl, &bv[0][0]);
                mma_bf16(oa[2 * g + 1], ph, &bv[0][2]);
                mma_bf16(oa[2 * g + 1], ph, &bv[1][2]);
                mma_bf16(oa[2 * g + 1], pl, &bv[0][2]);
            }
        }
        __syncthreads();
    }

    // ---- epilogue: O/l -> g_os hi/lo planes ([z][s][r] == flat reshape) ----
    const float i0 = 1.0f / l0r, i1 = 1.0f / l1r;
    #pragma unroll
    for (int b = 0; b < 8; b++) {
        const int r   = b * 8 + (lane & 3) * 2;
        const int r0w = s0 + wid * 16 + (lane >> 2);
        uint32_t hh, ll;
        size_t idx = zoff + (size_t)r0w * RR + r;
        splitpair(oa[b][0] * i0, oa[b][1] * i0, hh, ll);
        *reinterpret_cast<uint32_t*>(&g_os[0][idx]) = hh;
        *reinterpret_cast<uint32_t*>(&g_os[1][idx]) = ll;
        idx = zoff + (size_t)(r0w + 8) * RR + r;
        splitpair(oa[b][2] * i1, oa[b][3] * i1, hh, ll);
        *reinterpret_cast<uint32_t*>(&g_os[0][idx]) = hh;
        *reinterpret_cast<uint32_t*>(&g_os[1][idx]) = ll;
    }
    #undef QOFF
    #undef KOFF
    #undef VOFF
}

// ---------------------------------------------------------------------------
// Launch
// ---------------------------------------------------------------------------
extern "C" void kernel_launch(void* const* d_in, const int* in_sizes, int n_in,
                              void* d_out, int out_size)
{
    const float* q  = (const float*)d_in[0];
    const float* k  = (const float*)d_in[1];
    const float* v  = (const float*)d_in[2];
    const float* wq = (const float*)d_in[3];
    const float* wk = (const float*)d_in[4];
    const float* wv = (const float*)d_in[5];
    const float* wo = (const float*)d_in[6];
    float* out = (float*)d_out;

    (void)in_sizes; (void)n_in; (void)out_size;

    cudaFuncSetAttribute(gemm_kernel,
                         cudaFuncAttributeMaxDynamicSharedMemorySize, GEMM_SMEM);
    cudaFuncSetAttribute(attn_kernel,
                         cudaFuncAttributeMaxDynamicSharedMemorySize, ATT_SMEM);

    // 1) split inputs + weights to bf16 hi/lo
    conv_rows_kernel<<<2048, 256>>>(q, 0);
    conv_rows_kernel<<<2048, 256>>>(k, 1);
    conv_rows_kernel<<<2048, 256>>>(v, 2);
    conv_w_kernel<<<dim3(32, 32, 4), 256>>>(wq, wk, wv, wo);

    // 2) Q/K/V projections -> bf16 planes (Q pre-scaled by 1/8)
    gemm_kernel<<<dim3(8, 32, 3), 256, GEMM_SMEM>>>(nullptr, 0);

    // 3) tensor-core flash attention -> g_os planes
    attn_kernel<<<dim3(16, 32), 256, ATT_SMEM>>>();

    // 4) output projection -> fp32 out
    gemm_kernel<<<dim3(8, 32, 1), 256, GEMM_SMEM>>>(out, 3);
}

// round 9
// speedup vs baseline: 2.7521x; 1.1255x over previous
#include <cuda_runtime.h>
#include <cuda_bf16.h>
#include <cstdint>

// ---------------------------------------------------------------------------
// Problem constants
// ---------------------------------------------------------------------------
#define BB 2
#define SS 2048
#define DD 1024
#define HH 16
#define RR 64
#define BH (BB * HH)   // 32
#define NEL (BB * SS * DD)

// ---------------------------------------------------------------------------
// mma.sync helpers (baseline PTX, plain sm_100 target)
// ---------------------------------------------------------------------------
__device__ __forceinline__ uint32_t smem_u32(const void* p) {
    uint32_t a;
    asm("{ .reg .u64 t; cvta.to.shared.u64 t, %1; cvt.u32.u64 %0, t; }"
        : "=r"(a) : "l"(p));
    return a;
}
__device__ __forceinline__ void ldm_x4(uint32_t* r, uint32_t addr) {
    asm volatile("ldmatrix.sync.aligned.m8n8.x4.shared.b16 {%0,%1,%2,%3}, [%4];"
                 : "=r"(r[0]), "=r"(r[1]), "=r"(r[2]), "=r"(r[3]) : "r"(addr));
}
__device__ __forceinline__ void ldm_x4_t(uint32_t* r, uint32_t addr) {
    asm volatile("ldmatrix.sync.aligned.m8n8.x4.trans.shared.b16 {%0,%1,%2,%3}, [%4];"
                 : "=r"(r[0]), "=r"(r[1]), "=r"(r[2]), "=r"(r[3]) : "r"(addr));
}
__device__ __forceinline__ void mma_bf16(float* c, const uint32_t* a,
                                         const uint32_t* b) {
    asm volatile(
        "mma.sync.aligned.m16n8k16.row.col.f32.bf16.bf16.f32 "
        "{%0,%1,%2,%3}, {%4,%5,%6,%7}, {%8,%9}, {%0,%1,%2,%3};"
        : "+f"(c[0]), "+f"(c[1]), "+f"(c[2]), "+f"(c[3])
        : "r"(a[0]), "r"(a[1]), "r"(a[2]), "r"(a[3]), "r"(b[0]), "r"(b[1]));
}
__device__ __forceinline__ void cp16(uint32_t dst, const void* src) {
    asm volatile("cp.async.cg.shared.global [%0], [%1], 16;"
                 :: "r"(dst), "l"(__cvta_generic_to_global(src)));
}
#define CP_COMMIT() asm volatile("cp.async.commit_group;" ::: "memory")
#define CP_WAIT0()  asm volatile("cp.async.wait_group 0;" ::: "memory")
#define CP_WAIT1()  asm volatile("cp.async.wait_group 1;" ::: "memory")

__device__ __forceinline__ uint32_t swz(uint32_t o) { return o ^ ((o >> 3) & 0x70); }

// Split a float pair into bf16 hi/lo packed u32s.
__device__ __forceinline__ void splitpair(float x, float y,
                                          uint32_t& h, uint32_t& l) {
    __nv_bfloat16 hx = __float2bfloat16(x), hy = __float2bfloat16(y);
    __nv_bfloat16 lx = __float2bfloat16(x - __bfloat162float(hx));
    __nv_bfloat16 ly = __float2bfloat16(y - __bfloat162float(hy));
    __nv_bfloat162 H; H.x = hx; H.y = hy;
    __nv_bfloat162 L; L.x = lx; L.y = ly;
    h = *reinterpret_cast<uint32_t*>(&H);
    l = *reinterpret_cast<uint32_t*>(&L);
}

// ---------------------------------------------------------------------------
// Scratch
// ---------------------------------------------------------------------------
__device__ __nv_bfloat16 g_qs[2][NEL];
__device__ __nv_bfloat16 g_ks[2][NEL];
__device__ __nv_bfloat16 g_vs[2][NEL];
__device__ __nv_bfloat16 g_os[2][NEL];          // attn output splits
__device__ __nv_bfloat16 g_wqT[2][DD * DD];
__device__ __nv_bfloat16 g_wkT[2][DD * DD];
__device__ __nv_bfloat16 g_wvT[2][DD * DD];
__device__ __nv_bfloat16 g_woT[2][DD * DD];
// projection outputs as bf16 hi/lo planes, [b,h,s,r] layout (Q pre-scaled)
__device__ __nv_bfloat16 g_Qb[2][BH * SS * RR];
__device__ __nv_bfloat16 g_Kb[2][BH * SS * RR];
__device__ __nv_bfloat16 g_Vb[2][BH * SS * RR];

// ---------------------------------------------------------------------------
// fp32 -> 2-way bf16 split converters (vectorized: float4 in, uint2 out)
// ---------------------------------------------------------------------------
__global__ void __launch_bounds__(256) conv_rows_kernel(
    const float* __restrict__ src, int sel)
{
    __nv_bfloat16 *d0, *d1;
    if (sel == 0)      { d0 = g_qs[0]; d1 = g_qs[1]; }
    else if (sel == 1) { d0 = g_ks[0]; d1 = g_ks[1]; }
    else               { d0 = g_vs[0]; d1 = g_vs[1]; }

    for (int i = (blockIdx.x * blockDim.x + threadIdx.x) * 4; i < NEL;
         i += gridDim.x * blockDim.x * 4) {
        float4 x = *reinterpret_cast<const float4*>(src + i);
        uint32_t h0, l0, h1, l1;
        splitpair(x.x, x.y, h0, l0);
        splitpair(x.z, x.w, h1, l1);
        *reinterpret_cast<uint2*>(d0 + i) = make_uint2(h0, h1);
        *reinterpret_cast<uint2*>(d1 + i) = make_uint2(l0, l1);
    }
}

__global__ void __launch_bounds__(256) conv_w_kernel(
    const float* __restrict__ wq, const float* __restrict__ wk,
    const float* __restrict__ wv, const float* __restrict__ wo)
{
    const int sel = blockIdx.z;
    const float* W = (sel == 0) ? wq : (sel == 1) ? wk : (sel == 2) ? wv : wo;
    __nv_bfloat16 *d0, *d1;
    if (sel == 0)      { d0 = g_wqT[0]; d1 = g_wqT[1]; }
    else if (sel == 1) { d0 = g_wkT[0]; d1 = g_wkT[1]; }
    else if (sel == 2) { d0 = g_wvT[0]; d1 = g_wvT[1]; }
    else               { d0 = g_woT[0]; d1 = g_woT[1]; }

    __shared__ float tile[32][33];
    const int tx = threadIdx.x & 31;
    const int ty = threadIdx.x >> 5;
    const int ct = blockIdx.x;
    const int rt = blockIdx.y;

    #pragma unroll
    for (int i = 0; i < 4; i++) {
        const int d = rt * 32 + ty + i * 8;
        const int n = ct * 32 + tx;
        size_t idx;
        if (sel < 3) idx = ((size_t)(n >> 6) * DD + d) * RR + (n & 63);
        else         idx = (size_t)d * DD + n;
        tile[ty + i * 8][tx] = W[idx];
    }
    __syncthreads();
    #pragma unroll
    for (int i = 0; i < 4; i++) {
        const int nl = ty + i * 8;
        const int n  = ct * 32 + nl;
        const int d  = rt * 32 + tx;
        float x = tile[tx][nl];
        __nv_bfloat16 b0 = __float2bfloat16(x);
        size_t o = (size_t)n * DD + d;
        d0[o] = b0;
        d1[o] = __float2bfloat16(x - __bfloat162float(b0));
    }
}

// ---------------------------------------------------------------------------
// mma.sync split-bf16 GEMM.
//   kinds 0/1 (Q/K proj): 3 terms (hi*hi + hi*lo + lo*hi) -> bf16 planes
//   kind 2  (V proj):     3 terms -> bf16 planes
//   kind 3  (out proj):   3 terms -> fp32 outC
// ---------------------------------------------------------------------------
#define GEMM_SMEM 65536

__global__ void __launch_bounds__(256) gemm_kernel(float* __restrict__ outC,
                                                   int kind_base)
{
    const int kind = kind_base + blockIdx.z;
    const __nv_bfloat16 *Ax[2], *Bx[2];
    __nv_bfloat16 *P0 = nullptr, *P1 = nullptr;
    float scale = 1.0f;
    if (kind == 0)      { Ax[0] = g_qs[0]; Ax[1] = g_qs[1];
                          Bx[0] = g_wqT[0]; Bx[1] = g_wqT[1];
                          P0 = g_Qb[0]; P1 = g_Qb[1]; scale = 0.125f; }
    else if (kind == 1) { Ax[0] = g_ks[0]; Ax[1] = g_ks[1];
                          Bx[0] = g_wkT[0]; Bx[1] = g_wkT[1];
                          P0 = g_Kb[0]; P1 = g_Kb[1]; }
    else if (kind == 2) { Ax[0] = g_vs[0]; Ax[1] = g_vs[1];
                          Bx[0] = g_wvT[0]; Bx[1] = g_wvT[1];
                          P0 = g_Vb[0]; P1 = g_Vb[1]; }
    else                { Ax[0] = g_os[0]; Ax[1] = g_os[1];
                          Bx[0] = g_woT[0]; Bx[1] = g_woT[1]; }
    // 3-term schedule everywhere (lo*lo dropped; error ~2^-18, below the
    // split-storage residual that already dominates)
    const int ti[3] = {0, 0, 1};
    const int tj[3] = {0, 1, 0};
    const int NST = 48;

    extern __shared__ char smem[];
    const uint32_t sb = smem_u32(smem);
    const int t      = threadIdx.x;
    const int lane   = t & 31;
    const int wid    = t >> 5;
    const int warp_m = wid >> 2;
    const int warp_n = wid & 3;
    const int m0 = blockIdx.y * 128;
    const int n0 = blockIdx.x * 128;

    float acc[4][4][4];
    #pragma unroll
    for (int a = 0; a < 4; a++)
        #pragma unroll
        for (int b = 0; b < 4; b++)
            #pragma unroll
            for (int c = 0; c < 4; c++) acc[a][b][c] = 0.f;

    const int a_row  = warp_m * 64 + (lane & 15);
    const int a_koff = (lane >> 4) * 16;
    const int b_row  = warp_n * 32 + (lane & 7) + ((lane >> 4) & 1) * 8;
    const int b_koff = ((lane >> 3) & 1) * 16;

    {
        const __nv_bfloat16* Ag = Ax[0];
        const __nv_bfloat16* Bg = Bx[0];
        const uint32_t abase = sb, bbase = sb + 16384;
        #pragma unroll
        for (int it = 0; it < 4; it++) {
            const int cid = it * 256 + t;
            const int row = cid >> 3, c16 = cid & 7;
            cp16(abase + swz(row * 128 + c16 * 16),
                 Ag + (size_t)(m0 + row) * DD + c16 * 8);
            cp16(bbase + swz(row * 128 + c16 * 16),
                 Bg + (size_t)(n0 + row) * DD + c16 * 8);
        }
        CP_COMMIT();
    }

    for (int s = 0; s < NST; s++) {
        CP_WAIT0();
        __syncthreads();
        if (s + 1 < NST) {
            const int sn = s + 1;
            const int tt = sn >> 4;
            const int k0 = (sn & 15) * 64;
            const __nv_bfloat16* Ag = Ax[ti[tt]];
            const __nv_bfloat16* Bg = Bx[tj[tt]];
            const uint32_t abase = sb + (sn & 1) * 32768;
            const uint32_t bbase = abase + 16384;
            #pragma unroll
            for (int it = 0; it < 4; it++) {
                const int cid = it * 256 + t;
                const int row = cid >> 3, c16 = cid & 7;
                cp16(abase + swz(row * 128 + c16 * 16),
                     Ag + (size_t)(m0 + row) * DD + k0 + c16 * 8);
                cp16(bbase + swz(row * 128 + c16 * 16),
                     Bg + (size_t)(n0 + row) * DD + k0 + c16 * 8);
            }
            CP_COMMIT();
        }
        const uint32_t abase = sb + (s & 1) * 32768;
        const uint32_t bbase = abase + 16384;
        #pragma unroll
        for (int k16 = 0; k16 < 64; k16 += 16) {
            uint32_t ar[4][4], br[4][2];
            #pragma unroll
            for (int mi = 0; mi < 4; mi++) {
                const int row = a_row + mi * 16;
                ldm_x4(ar[mi], abase + swz(row * 128 + k16 * 2 + a_koff));
            }
            #pragma unroll
            for (int nb = 0; nb < 2; nb++) {
                const int n = b_row + nb * 16;
                uint32_t r[4];
                ldm_x4(r, bbase + swz(n * 128 + k16 * 2 + b_koff));
                br[nb * 2][0] = r[0]; br[nb * 2][1] = r[1];
                br[nb * 2 + 1][0] = r[2]; br[nb * 2 + 1][1] = r[3];
            }
            #pragma unroll
            for (int mi = 0; mi < 4; mi++)
                #pragma unroll
                for (int ni = 0; ni < 4; ni++)
                    mma_bf16(acc[mi][ni], ar[mi], br[ni]);
        }
    }

    // epilogue
    #pragma unroll
    for (int mi = 0; mi < 4; mi++) {
        #pragma unroll
        for (int ni = 0; ni < 4; ni++) {
            const int r0 = m0 + warp_m * 64 + mi * 16 + (lane >> 2);
            const int c  = n0 + warp_n * 32 + ni * 8 + (lane & 3) * 2;
            #pragma unroll
            for (int half = 0; half < 2; half++) {
                const int m = r0 + half * 8;
                float v0 = acc[mi][ni][half * 2] * scale;
                float v1 = acc[mi][ni][half * 2 + 1] * scale;
                if (kind < 3) {
                    const int h = c >> 6, r = c & 63;
                    const int b = m >> 11, sl = m & 2047;
                    size_t idx = (((size_t)b * HH + h) * SS + sl) * RR + r;
                    uint32_t hh, ll;
                    splitpair(v0, v1, hh, ll);
                    *reinterpret_cast<uint32_t*>(&P0[idx]) = hh;
                    *reinterpret_cast<uint32_t*>(&P1[idx]) = ll;
                } else {
                    *reinterpret_cast<float2*>(&outC[(size_t)m * DD + c]) =
                        make_float2(v0, v1);
                }
            }
        }
    }
}

// ---------------------------------------------------------------------------
// Tensor-core flash attention (same structure as the 733us version;
// GEMM1 now 3 split terms: hi*hi + hi*lo + lo*hi).
// ---------------------------------------------------------------------------
#define ATT_SMEM 98304

__global__ void __launch_bounds__(256, 2) attn_kernel()
{
    const int z  = blockIdx.y;
    const int s0 = blockIdx.x * 128;
    extern __shared__ char sm[];
    const uint32_t sb = smem_u32(sm);
    const int t = threadIdx.x, lane = t & 31, wid = t >> 5;
    const size_t zoff = (size_t)z * SS * RR;

    #define QOFF(p)      (sb + (p) * 16384u)
    #define KOFF(bf, p)  (sb + 32768u + (bf) * 32768u + (p) * 8192u)
    #define VOFF(bf, p)  (sb + 32768u + (bf) * 32768u + 16384u + (p) * 8192u)

    #pragma unroll
    for (int p = 0; p < 2; p++) {
        const __nv_bfloat16* src = g_Qb[p] + zoff + (size_t)s0 * RR;
        #pragma unroll
        for (int it = 0; it < 4; it++) {
            const int cid = it * 256 + t;
            const int row = cid >> 3, c16 = cid & 7;
            cp16(QOFF(p) + swz(row * 128 + c16 * 16), src + row * 64 + c16 * 8);
        }
    }
    #pragma unroll
    for (int p = 0; p < 2; p++) {
        #pragma unroll
        for (int it = 0; it < 2; it++) {
            const int cid = it * 256 + t;
            const int row = cid >> 3, c16 = cid & 7;
            cp16(KOFF(0, p) + swz(row * 128 + c16 * 16),
                 g_Kb[p] + zoff + (size_t)row * RR + c16 * 8);
            cp16(VOFF(0, p) + swz(row * 128 + c16 * 16),
                 g_Vb[p] + zoff + (size_t)row * RR + c16 * 8);
        }
    }
    CP_COMMIT();

    float m0r = -3.0e38f, m1r = -3.0e38f, l0r = 0.f, l1r = 0.f;
    float oa[8][4];
    #pragma unroll
    for (int b = 0; b < 8; b++)
        #pragma unroll
        for (int c = 0; c < 4; c++) oa[b][c] = 0.f;

    for (int s = 0; s < 32; s++) {
        const int buf = s & 1;
        if (s + 1 < 32) {
            const int nb = (s + 1) & 1;
            const int kv = (s + 1) * 64;
            #pragma unroll
            for (int p = 0; p < 2; p++) {
                #pragma unroll
                for (int it = 0; it < 2; it++) {
                    const int cid = it * 256 + t;
                    const int row = cid >> 3, c16 = cid & 7;
                    cp16(KOFF(nb, p) + swz(row * 128 + c16 * 16),
                         g_Kb[p] + zoff + (size_t)(kv + row) * RR + c16 * 8);
                    cp16(VOFF(nb, p) + swz(row * 128 + c16 * 16),
                         g_Vb[p] + zoff + (size_t)(kv + row) * RR + c16 * 8);
                }
            }
            CP_COMMIT();
            CP_WAIT1();
        } else {
            CP_WAIT0();
        }
        __syncthreads();

        // ---- GEMM1: S = Q K^T (3 split terms) ----
        float sa[8][4];
        #pragma unroll
        for (int b = 0; b < 8; b++)
            #pragma unroll
            for (int c = 0; c < 4; c++) sa[b][c] = 0.f;

        #pragma unroll
        for (int kb = 0; kb < 4; kb++) {
            uint32_t aq[2][4];
            const int arow = wid * 16 + (lane & 15);
            const int akoff = kb * 32 + (lane >> 4) * 16;
            #pragma unroll
            for (int p = 0; p < 2; p++)
                ldm_x4(aq[p], QOFF(p) + swz(arow * 128 + akoff));
            #pragma unroll
            for (int g = 0; g < 4; g++) {
                uint32_t bk[2][4];
                const int brow = g * 16 + (lane & 7) + ((lane >> 4) & 1) * 8;
                const int bkoff = kb * 32 + ((lane >> 3) & 1) * 16;
                #pragma unroll
                for (int p = 0; p < 2; p++)
                    ldm_x4(bk[p], KOFF(buf, p) + swz(brow * 128 + bkoff));
                // hi*hi
                mma_bf16(sa[2 * g],     aq[0], &bk[0][0]);
                mma_bf16(sa[2 * g + 1], aq[0], &bk[0][2]);
                // hi*lo
                mma_bf16(sa[2 * g],     aq[0], &bk[1][0]);
                mma_bf16(sa[2 * g + 1], aq[0], &bk[1][2]);
                // lo*hi
                mma_bf16(sa[2 * g],     aq[1], &bk[0][0]);
                mma_bf16(sa[2 * g + 1], aq[1], &bk[0][2]);
            }
        }

        // ---- online softmax ----
        float mt0 = -3.0e38f, mt1 = -3.0e38f;
        #pragma unroll
        for (int b = 0; b < 8; b++) {
            mt0 = fmaxf(mt0, fmaxf(sa[b][0], sa[b][1]));
            mt1 = fmaxf(mt1, fmaxf(sa[b][2], sa[b][3]));
        }
        mt0 = fmaxf(mt0, __shfl_xor_sync(0xffffffffu, mt0, 1));
        mt0 = fmaxf(mt0, __shfl_xor_sync(0xffffffffu, mt0, 2));
        mt1 = fmaxf(mt1, __shfl_xor_sync(0xffffffffu, mt1, 1));
        mt1 = fmaxf(mt1, __shfl_xor_sync(0xffffffffu, mt1, 2));
        const float mn0 = fmaxf(m0r, mt0), mn1 = fmaxf(m1r, mt1);
        const float al0 = __expf(m0r - mn0), al1 = __expf(m1r - mn1);
        m0r = mn0; m1r = mn1;
        float rs0 = 0.f, rs1 = 0.f;
        #pragma unroll
        for (int b = 0; b < 8; b++) {
            sa[b][0] = __expf(sa[b][0] - mn0);
            sa[b][1] = __expf(sa[b][1] - mn0);
            sa[b][2] = __expf(sa[b][2] - mn1);
            sa[b][3] = __expf(sa[b][3] - mn1);
            rs0 += sa[b][0] + sa[b][1];
            rs1 += sa[b][2] + sa[b][3];
        }
        rs0 += __shfl_xor_sync(0xffffffffu, rs0, 1);
        rs0 += __shfl_xor_sync(0xffffffffu, rs0, 2);
        rs1 += __shfl_xor_sync(0xffffffffu, rs1, 1);
        rs1 += __shfl_xor_sync(0xffffffffu, rs1, 2);
        l0r = l0r * al0 + rs0;
        l1r = l1r * al1 + rs1;
        #pragma unroll
        for (int b = 0; b < 8; b++) {
            oa[b][0] *= al0; oa[b][1] *= al0;
            oa[b][2] *= al1; oa[b][3] *= al1;
        }

        // ---- GEMM2: O += P V (3 split terms) ----
        #pragma unroll
        for (int kb = 0; kb < 4; kb++) {
            uint32_t ph[4], pl[4];
            splitpair(sa[2 * kb][0],     sa[2 * kb][1],     ph[0], pl[0]);
            splitpair(sa[2 * kb][2],     sa[2 * kb][3],     ph[1], pl[1]);
            splitpair(sa[2 * kb + 1][0], sa[2 * kb + 1][1], ph[2], pl[2]);
            splitpair(sa[2 * kb + 1][2], sa[2 * kb + 1][3], ph[3], pl[3]);
            #pragma unroll
            for (int g = 0; g < 4; g++) {
                uint32_t bv[2][4];
                const int trow = kb * 16 + (lane & 7) + ((lane >> 3) & 1) * 8;
                const int rbyte = g * 32 + ((lane >> 4) & 1) * 16;
                #pragma unroll
                for (int p = 0; p < 2; p++)
                    ldm_x4_t(bv[p], VOFF(buf, p) + swz(trow * 128 + rbyte));
                mma_bf16(oa[2 * g], ph, &bv[0][0]);
                mma_bf16(oa[2 * g], ph, &bv[1][0]);
                mma_bf16(oa[2 * g], pl, &bv[0][0]);
                mma_bf16(oa[2 * g + 1], ph, &bv[0][2]);
                mma_bf16(oa[2 * g + 1], ph, &bv[1][2]);
                mma_bf16(oa[2 * g + 1], pl, &bv[0][2]);
            }
        }
        __syncthreads();
    }

    // ---- epilogue ----
    const float i0 = 1.0f / l0r, i1 = 1.0f / l1r;
    #pragma unroll
    for (int b = 0; b < 8; b++) {
        const int r   = b * 8 + (lane & 3) * 2;
        const int r0w = s0 + wid * 16 + (lane >> 2);
        uint32_t hh, ll;
        size_t idx = zoff + (size_t)r0w * RR + r;
        splitpair(oa[b][0] * i0, oa[b][1] * i0, hh, ll);
        *reinterpret_cast<uint32_t*>(&g_os[0][idx]) = hh;
        *reinterpret_cast<uint32_t*>(&g_os[1][idx]) = ll;
        idx = zoff + (size_t)(r0w + 8) * RR + r;
        splitpair(oa[b][2] * i1, oa[b][3] * i1, hh, ll);
        *reinterpret_cast<uint32_t*>(&g_os[0][idx]) = hh;
        *reinterpret_cast<uint32_t*>(&g_os[1][idx]) = ll;
    }
    #undef QOFF
    #undef KOFF
    #undef VOFF
}

// ---------------------------------------------------------------------------
// Launch
// ---------------------------------------------------------------------------
extern "C" void kernel_launch(void* const* d_in, const int* in_sizes, int n_in,
                              void* d_out, int out_size)
{
    const float* q  = (const float*)d_in[0];
    const float* k  = (const float*)d_in[1];
    const float* v  = (const float*)d_in[2];
    const float* wq = (const float*)d_in[3];
    const float* wk = (const float*)d_in[4];
    const float* wv = (const float*)d_in[5];
    const float* wo = (const float*)d_in[6];
    float* out = (float*)d_out;

    (void)in_sizes; (void)n_in; (void)out_size;

    cudaFuncSetAttribute(gemm_kernel,
                         cudaFuncAttributeMaxDynamicSharedMemorySize, GEMM_SMEM);
    cudaFuncSetAttribute(attn_kernel,
                         cudaFuncAttributeMaxDynamicSharedMemorySize, ATT_SMEM);

    // 1) split inputs + weights to bf16 hi/lo
    conv_rows_kernel<<<1024, 256>>>(q, 0);
    conv_rows_kernel<<<1024, 256>>>(k, 1);
    conv_rows_kernel<<<1024, 256>>>(v, 2);
    conv_w_kernel<<<dim3(32, 32, 4), 256>>>(wq, wk, wv, wo);

    // 2) Q/K/V projections -> bf16 planes (Q pre-scaled by 1/8)
    gemm_kernel<<<dim3(8, 32, 3), 256, GEMM_SMEM>>>(nullptr, 0);

    // 3) tensor-core flash attention -> g_os planes
    attn_kernel<<<dim3(16, 32), 256, ATT_SMEM>>>();

    // 4) output projection -> fp32 out
    gemm_kernel<<<dim3(8, 32, 1), 256, GEMM_SMEM>>>(out, 3);
}